// round 13
// baseline (speedup 1.0000x reference)
#include <cuda_runtime.h>
#include <cuda_fp16.h>
#include <cstdint>

#define N_NODES 100000
#define N_EDGES 1600000
#define CAP 64            // per-node neighbor bucket capacity (mean deg 16)

// -------- device scratch (static: no allocations allowed) --------
__device__ int   g_cursor[N_NODES];
__device__ int   g_col[N_NODES * CAP];
__device__ __align__(16) __half2 g_x16[N_NODES * 32];   // x in fp16 (64 ch)
__device__ __align__(16) __half2 g_h16[N_NODES * 64];   // h1 in fp16 (128 ch)
__device__ __align__(16) __half  g_z1h[N_NODES * 64];   // z1 fp16
__device__ __align__(16) __half  g_z2h[N_NODES * 128];  // z2 fp16
// transposed fp16 weights [ch][k], compact: offsets in halfs:
// W1a_t:0 (128x64)  W1b_t:8192 (128x128)  W2a_t:24576  W2b_t:40960  Wlin_t:57344 (64x128)
__device__ __align__(16) __half g_wt16[65536];

// m16n8k16 fp16 MMA, fp32 accumulate (sm_70+ PTX, plain sm_103 OK)
__device__ __forceinline__ void mma_f16(float c[4],
                                        uint32_t a0, uint32_t a1,
                                        uint32_t a2, uint32_t a3,
                                        uint32_t b0, uint32_t b1) {
    asm volatile(
        "mma.sync.aligned.m16n8k16.row.col.f32.f16.f16.f32 "
        "{%0,%1,%2,%3}, {%4,%5,%6,%7}, {%8,%9}, {%0,%1,%2,%3};"
        : "+f"(c[0]), "+f"(c[1]), "+f"(c[2]), "+f"(c[3])
        : "r"(a0), "r"(a1), "r"(a2), "r"(a3), "r"(b0), "r"(b1));
}

__device__ __forceinline__ uint32_t sm_u32(const void* p) {
    return (uint32_t)__cvta_generic_to_shared(p);
}

// ldmatrix x4: 4 8x8 b16 matrices (sm_75+, not arch-'a'-gated)
__device__ __forceinline__ void ldsm4(uint32_t r[4], uint32_t addr) {
    asm volatile("ldmatrix.sync.aligned.m8n8.x4.shared.b16 {%0,%1,%2,%3}, [%4];"
                 : "=r"(r[0]), "=r"(r[1]), "=r"(r[2]), "=r"(r[3]) : "r"(addr));
}

// MMA over K with ldmatrix fragment loads. A halfs [row][ASTR], B^T halfs [ch][BSTR].
// Warp covers rows row0..row0+15, channels 0..NT*8-1.
template <int K, int ASTR, int BSTR, int NT>
__device__ __forceinline__ void do_mma16(const __half* __restrict__ As,
                                         const __half* __restrict__ Bs,
                                         float (&acc)[NT][4], int row0) {
    int lane = threadIdx.x & 31;
    int lr = lane & 7, sel = lane >> 3;           // sel: matrix index 0..3
    // A x4: M0 rows0-7/k0-7, M1 rows8-15/k0-7, M2 rows0-7/k8-15, M3 rows8-15/k8-15
    uint32_t a_base = sm_u32(As + (row0 + lr + (sel & 1) * 8) * ASTR + (sel >> 1) * 8);
    // B x4: M0 n(2tp*8..)/k0-7, M1 same/k8-15, M2 n((2tp+1)*8..)/k0-7, M3 same/k8-15
    uint32_t b_base = sm_u32(Bs + ((sel >> 1) * 8 + lr) * BSTR + (sel & 1) * 8);
#pragma unroll
    for (int kb = 0; kb < K / 16; kb++) {
        uint32_t af[4];
        ldsm4(af, a_base + kb * 32);              // +16 halfs = 32B per k-block
#pragma unroll
        for (int tp = 0; tp < NT / 2; tp++) {
            uint32_t bf[4];
            ldsm4(bf, b_base + (uint32_t)(tp * 16 * BSTR * 2 + kb * 32));
            mma_f16(acc[2 * tp],     af[0], af[1], af[2], af[3], bf[0], bf[1]);
            mma_f16(acc[2 * tp + 1], af[0], af[1], af[2], af[3], bf[2], bf[3]);
        }
    }
}

// MMA with A fragments resident in registers; B via ldmatrix.
template <int NKB, int BSTR, int NT>
__device__ __forceinline__ void do_mma16_regA(const uint32_t (&af)[NKB][4],
                                              const __half* __restrict__ Bs,
                                              float (&acc)[NT][4]) {
    int lane = threadIdx.x & 31;
    int lr = lane & 7, sel = lane >> 3;
    uint32_t b_base = sm_u32(Bs + ((sel >> 1) * 8 + lr) * BSTR + (sel & 1) * 8);
#pragma unroll
    for (int kb = 0; kb < NKB; kb++) {
#pragma unroll
        for (int tp = 0; tp < NT / 2; tp++) {
            uint32_t bf[4];
            ldsm4(bf, b_base + (uint32_t)(tp * 16 * BSTR * 2 + kb * 32));
            mma_f16(acc[2 * tp],     af[kb][0], af[kb][1], af[kb][2], af[kb][3], bf[0], bf[1]);
            mma_f16(acc[2 * tp + 1], af[kb][0], af[kb][1], af[kb][2], af[kb][3], bf[2], bf[3]);
        }
    }
}

// relu(acc + bias) -> fp16 A-fragments for the next stage (pure register permute).
template <int NKB>
__device__ __forceinline__ void acc_to_afrag(const float (&acc)[2 * NKB][4],
                                             uint32_t (&af)[NKB][4],
                                             const float* __restrict__ bias) {
    int tg = threadIdx.x & 3;
#pragma unroll
    for (int kb = 0; kb < NKB; kb++) {
        int t0 = 2 * kb, t1 = 2 * kb + 1;
        float b00 = bias[t0 * 8 + 2 * tg], b01 = bias[t0 * 8 + 2 * tg + 1];
        float b10 = bias[t1 * 8 + 2 * tg], b11 = bias[t1 * 8 + 2 * tg + 1];
        __half2 h;
        h = __floats2half2_rn(fmaxf(acc[t0][0] + b00, 0.f), fmaxf(acc[t0][1] + b01, 0.f));
        af[kb][0] = *(uint32_t*)&h;
        h = __floats2half2_rn(fmaxf(acc[t0][2] + b00, 0.f), fmaxf(acc[t0][3] + b01, 0.f));
        af[kb][1] = *(uint32_t*)&h;
        h = __floats2half2_rn(fmaxf(acc[t1][0] + b10, 0.f), fmaxf(acc[t1][1] + b11, 0.f));
        af[kb][2] = *(uint32_t*)&h;
        h = __floats2half2_rn(fmaxf(acc[t1][2] + b10, 0.f), fmaxf(acc[t1][3] + b11, 0.f));
        af[kb][3] = *(uint32_t*)&h;
    }
}

// Epilogue -> global fp32 (final out): acc + bias, float2 stores, row-guarded
template <int NT, int NOUT>
__device__ __forceinline__ void st_glob(float* __restrict__ out,
                                        float (&acc)[NT][4], int grow0,
                                        const float* __restrict__ bias, int n) {
    int lane = threadIdx.x & 31;
    int g = lane >> 2, tg = lane & 3;
    int r0 = grow0 + g, r1 = r0 + 8;
#pragma unroll
    for (int t = 0; t < NT; t++) {
        int ch = t * 8 + 2 * tg;
        float bx = bias[ch], by = bias[ch + 1];
        if (r0 < n) *(float2*)&out[r0 * NOUT + ch] = make_float2(acc[t][0] + bx, acc[t][1] + by);
        if (r1 < n) *(float2*)&out[r1 * NOUT + ch] = make_float2(acc[t][2] + bx, acc[t][3] + by);
    }
}

// Epilogue -> global fp16 (h1): relu(acc + bias) as half2, row-guarded
template <int NT>
__device__ __forceinline__ void st_glob_h16(__half2* __restrict__ out,
                                            float (&acc)[NT][4], int grow0,
                                            const float* __restrict__ bias, int n) {
    int lane = threadIdx.x & 31;
    int g = lane >> 2, tg = lane & 3;
    int r0 = grow0 + g, r1 = r0 + 8;
#pragma unroll
    for (int t = 0; t < NT; t++) {
        int ch = t * 8 + 2 * tg;      // even
        float bx = bias[ch], by = bias[ch + 1];
        if (r0 < n) out[r0 * 64 + (ch >> 1)] =
            __floats2half2_rn(fmaxf(acc[t][0] + bx, 0.f), fmaxf(acc[t][1] + by, 0.f));
        if (r1 < n) out[r1 * 64 + (ch >> 1)] =
            __floats2half2_rn(fmaxf(acc[t][2] + bx, 0.f), fmaxf(acc[t][3] + by, 0.f));
    }
}

// ==================== init: zero cursors + transposed fp16 weights ====================
__global__ void k_init(const float* __restrict__ W1a, const float* __restrict__ W1b,
                       const float* __restrict__ W2a, const float* __restrict__ W2b,
                       const float* __restrict__ Wlin) {
    int i = blockIdx.x * 256 + threadIdx.x;
    if (i < N_NODES) g_cursor[i] = 0;
    if (i < 65536) {
        float v;
        if (i < 8192)       { int ch = i >> 6, k = i & 63;              v = W1a[k * 128 + ch]; }
        else if (i < 24576) { int j = i - 8192;  int ch = j >> 7, k = j & 127; v = W1b[k * 128 + ch]; }
        else if (i < 40960) { int j = i - 24576; int ch = j >> 7, k = j & 127; v = W2a[k * 128 + ch]; }
        else if (i < 57344) { int j = i - 40960; int ch = j >> 7, k = j & 127; v = W2b[k * 128 + ch]; }
        else                { int j = i - 57344; int ch = j >> 7, k = j & 127; v = Wlin[k * 64 + ch]; }
        g_wt16[i] = __float2half(v);
    }
}

// ==================== bucket fill (no scan) + x -> fp16 convert ====================
__global__ void k_fill(const int* __restrict__ ei, const float* __restrict__ x) {
    int e = blockIdx.x * 256 + threadIdx.x;     // 1.6M threads
    if (e < N_EDGES) {
        int d = ei[N_EDGES + e];
        int s = ei[e];
        int p = atomicAdd(&g_cursor[d], 1);
        if (p < CAP) g_col[d * CAP + p] = s;
    }
    const float4* x4 = (const float4*)x;
    float4 v = x4[e];                            // e < 1.6M exactly covers x
    g_x16[e * 2]     = __floats2half2_rn(v.x, v.y);
    g_x16[e * 2 + 1] = __floats2half2_rn(v.z, v.w);
}

// ==================== Aggregation (fp16 gather, fp32 accumulate) ====================

// d=64: warp per node; 16 lanes x uint2 = one 128B line/edge; half-warp interleave.
__global__ void __launch_bounds__(256) k_agg64(const float* __restrict__ x) {
    int node = (blockIdx.x * 256 + threadIdx.x) >> 5;
    int lane = threadIdx.x & 31;
    int c = lane & 15;
    int h = lane >> 4;
    int deg = min(g_cursor[node], CAP);
    int base = node * CAP;
    float4 acc = make_float4(0.f, 0.f, 0.f, 0.f);
    const uint2* x16 = (const uint2*)g_x16;
    for (int p = h; p < deg; p += 2) {
        int s = __ldg(&g_col[base + p]);
        uint2 u = x16[s * 16 + c];
        float2 f0 = __half22float2(*(__half2*)&u.x);
        float2 f1 = __half22float2(*(__half2*)&u.y);
        acc.x += f0.x; acc.y += f0.y; acc.z += f1.x; acc.w += f1.y;
    }
    acc.x += __shfl_xor_sync(0xffffffffu, acc.x, 16);
    acc.y += __shfl_xor_sync(0xffffffffu, acc.y, 16);
    acc.z += __shfl_xor_sync(0xffffffffu, acc.z, 16);
    acc.w += __shfl_xor_sync(0xffffffffu, acc.w, 16);
    if (h == 0) {
        float4 xi = ((const float4*)x)[node * 16 + c];
        uint2 o;
        *(__half2*)&o.x = __floats2half2_rn(xi.x + acc.x, xi.y + acc.y);
        *(__half2*)&o.y = __floats2half2_rn(xi.z + acc.z, xi.w + acc.w);
        ((uint2*)g_z1h)[node * 16 + c] = o;
    }
}

// d=128: warp per node; 32 lanes x uint2 = 256B/edge; unroll 2.
__global__ void __launch_bounds__(256) k_agg128() {
    int node = (blockIdx.x * 256 + threadIdx.x) >> 5;
    int lane = threadIdx.x & 31;
    int deg = min(g_cursor[node], CAP);
    int base = node * CAP;
    const uint2* h16 = (const uint2*)g_h16;
    float4 a0 = make_float4(0.f, 0.f, 0.f, 0.f);
    float4 a1 = make_float4(0.f, 0.f, 0.f, 0.f);
    int p = 0;
    for (; p + 1 < deg; p += 2) {
        int s0 = __ldg(&g_col[base + p]);
        int s1 = __ldg(&g_col[base + p + 1]);
        uint2 u0 = h16[s0 * 32 + lane];
        uint2 u1 = h16[s1 * 32 + lane];
        float2 f00 = __half22float2(*(__half2*)&u0.x);
        float2 f01 = __half22float2(*(__half2*)&u0.y);
        float2 f10 = __half22float2(*(__half2*)&u1.x);
        float2 f11 = __half22float2(*(__half2*)&u1.y);
        a0.x += f00.x; a0.y += f00.y; a0.z += f01.x; a0.w += f01.y;
        a1.x += f10.x; a1.y += f10.y; a1.z += f11.x; a1.w += f11.y;
    }
    if (p < deg) {
        int s0 = __ldg(&g_col[base + p]);
        uint2 u0 = h16[s0 * 32 + lane];
        float2 f00 = __half22float2(*(__half2*)&u0.x);
        float2 f01 = __half22float2(*(__half2*)&u0.y);
        a0.x += f00.x; a0.y += f00.y; a0.z += f01.x; a0.w += f01.y;
    }
    uint2 us = h16[node * 32 + lane];
    float2 s0 = __half22float2(*(__half2*)&us.x);
    float2 s1 = __half22float2(*(__half2*)&us.y);
    uint2 o;
    *(__half2*)&o.x = __floats2half2_rn(s0.x + a0.x + a1.x, s0.y + a0.y + a1.y);
    *(__half2*)&o.y = __floats2half2_rn(s1.x + a0.z + a1.z, s1.y + a0.w + a1.w);
    ((uint2*)g_z2h)[node * 32 + lane] = o;
}

// ==================== Fused MLP kernels (ldmatrix + register-resident mid) ==========
// 256 threads = 8 warps; warp w owns rows w*16..w*16+15, ALL 128 output channels.

// conv1: h1(fp16) = relu( relu(z1@W1a+b1a) @ W1b + b1b )
__global__ void __launch_bounds__(256, 2)
k_mlp1(const float* __restrict__ b1a, const float* __restrict__ b1b, int n) {
    extern __shared__ __align__(16) char smraw[];
    __half* A   = (__half*)smraw;            // 128 x 72  (z1 tile)
    __half* WaT = A + 128 * 72;              // 128 x 72  (W1a^T [ch][k])
    __half* WbT = WaT + 128 * 72;            // 128 x 136 (W1b^T)

    int tid = threadIdx.x;
    int m0 = blockIdx.x * 128;

    for (int i = tid; i < 128 * 16; i += 256) {
        int row = i >> 4, j = i & 15;
        int node = m0 + row;
        uint2 v = make_uint2(0u, 0u);
        if (node < n) v = ((const uint2*)g_z1h)[node * 16 + j];
        *(uint2*)&A[row * 72 + j * 4] = v;
    }
    for (int i = tid; i < 128 * 16; i += 256) {
        int ch = i >> 4, j = i & 15;
        *(uint2*)&WaT[ch * 72 + j * 4] = ((const uint2*)g_wt16)[i];
    }
    for (int i = tid; i < 128 * 16; i += 256) {
        int ch = i >> 4, j = i & 15;
        *(uint4*)&WbT[ch * 136 + j * 8] = ((const uint4*)(g_wt16 + 8192))[i];
    }
    __syncthreads();

    int row0 = (tid >> 5) * 16;

    float acc1[16][4];
#pragma unroll
    for (int t = 0; t < 16; t++)
        acc1[t][0] = acc1[t][1] = acc1[t][2] = acc1[t][3] = 0.f;
    do_mma16<64, 72, 72, 16>(A, WaT, acc1, row0);

    uint32_t af[8][4];
    acc_to_afrag<8>(acc1, af, b1a);

    float acc2[16][4];
#pragma unroll
    for (int t = 0; t < 16; t++)
        acc2[t][0] = acc2[t][1] = acc2[t][2] = acc2[t][3] = 0.f;
    do_mma16_regA<8, 136, 16>(af, WbT, acc2);
    st_glob_h16<16>(g_h16, acc2, m0 + row0, b1b, n);
}

// conv2 + final: out = relu( relu(z2@W2a+b2a) @ W2b + b2b ) @ Wlin + blin
__global__ void __launch_bounds__(256, 2)
k_mlp2(const float* __restrict__ b2a, const float* __restrict__ b2b,
       const float* __restrict__ blin, float* __restrict__ out, int n) {
    extern __shared__ __align__(16) char smraw[];
    __half* RA = (__half*)smraw;             // 128 x 136 : z2 tile
    __half* RB = RA + 128 * 136;             // 128 x 136 : W2aT -> WlinT
    __half* RC = RB + 128 * 136;             // 128 x 136 : W2bT

    int tid = threadIdx.x;
    int m0 = blockIdx.x * 128;

    for (int i = tid; i < 128 * 16; i += 256) {
        int row = i >> 4, j = i & 15;
        int node = m0 + row;
        uint4 v = make_uint4(0u, 0u, 0u, 0u);
        if (node < n) v = ((const uint4*)g_z2h)[node * 16 + j];
        *(uint4*)&RA[row * 136 + j * 8] = v;
    }
    for (int i = tid; i < 128 * 16; i += 256) {
        int ch = i >> 4, j = i & 15;
        *(uint4*)&RB[ch * 136 + j * 8] = ((const uint4*)(g_wt16 + 24576))[i];
        *(uint4*)&RC[ch * 136 + j * 8] = ((const uint4*)(g_wt16 + 40960))[i];
    }
    __syncthreads();

    int row0 = (tid >> 5) * 16;

    // stage 1: mid = relu(z2 @ W2a + b2a)   (mid -> registers)
    float acc1[16][4];
#pragma unroll
    for (int t = 0; t < 16; t++)
        acc1[t][0] = acc1[t][1] = acc1[t][2] = acc1[t][3] = 0.f;
    do_mma16<128, 136, 136, 16>(RA, RB, acc1, row0);
    uint32_t af1[8][4];
    acc_to_afrag<8>(acc1, af1, b2a);
    __syncthreads();                 // all reads of RB (W2aT) done

    // overlap: load WlinT into RB while stage-2 MMAs run
    for (int i = tid; i < 64 * 16; i += 256) {
        int ch = i >> 4, j = i & 15;
        *(uint4*)&RB[ch * 136 + j * 8] = ((const uint4*)(g_wt16 + 57344))[i];
    }

    // stage 2: h = relu(mid @ W2b + b2b)    (h -> registers)
    float acc2[16][4];
#pragma unroll
    for (int t = 0; t < 16; t++)
        acc2[t][0] = acc2[t][1] = acc2[t][2] = acc2[t][3] = 0.f;
    do_mma16_regA<8, 136, 16>(af1, RC, acc2);
    uint32_t af2[8][4];
    acc_to_afrag<8>(acc2, af2, b2b);
    __syncthreads();                 // WlinT visible

    // stage 3: out = h @ Wlin + blin   (NOUT=64, NT=8)
    float acc3[8][4];
#pragma unroll
    for (int t = 0; t < 8; t++)
        acc3[t][0] = acc3[t][1] = acc3[t][2] = acc3[t][3] = 0.f;
    do_mma16_regA<8, 136, 8>(af2, RB, acc3);
    st_glob<8, 64>(out, acc3, m0 + row0, blin, n);
}

// ==================== host orchestration ====================

extern "C" void kernel_launch(void* const* d_in, const int* in_sizes, int n_in,
                              void* d_out, int out_size) {
    const float* x    = (const float*)d_in[0];
    const int*   ei   = (const int*)d_in[1];
    const float* W1a  = (const float*)d_in[2];
    const float* b1a  = (const float*)d_in[3];
    const float* W1b  = (const float*)d_in[4];
    const float* b1b  = (const float*)d_in[5];
    const float* W2a  = (const float*)d_in[6];
    const float* b2a  = (const float*)d_in[7];
    const float* W2b  = (const float*)d_in[8];
    const float* b2b  = (const float*)d_in[9];
    const float* Wlin = (const float*)d_in[10];
    const float* blin = (const float*)d_in[11];
    float*       out  = (float*)d_out;

    const int SM1 = (128 * 72 + 128 * 72 + 128 * 136) * 2;   // 71680
    const int SM2 = (3 * 128 * 136) * 2;                     // 104448
    cudaFuncSetAttribute(k_mlp1, cudaFuncAttributeMaxDynamicSharedMemorySize, SM1);
    cudaFuncSetAttribute(k_mlp2, cudaFuncAttributeMaxDynamicSharedMemorySize, SM2);

    const int GN   = (N_NODES + 255) / 256;   // 391
    const int GE   = (N_EDGES + 255) / 256;   // 6250
    const int GW   = N_NODES / 8;             // 12500
    const int GB128 = (N_NODES + 127) / 128;  // 782

    // --- init + bucket fill (+ x->fp16) ---
    k_init<<<GN, 256>>>(W1a, W1b, W2a, W2b, Wlin);
    k_fill<<<GE, 256>>>(ei, x);

    // --- conv1 ---
    k_agg64<<<GW, 256>>>(x);
    k_mlp1<<<GB128, 256, SM1>>>(b1a, b1b, N_NODES);

    // --- conv2 + final projection ---
    k_agg128<<<GW, 256>>>();
    k_mlp2<<<GB128, 256, SM2>>>(b2a, b2b, blin, out, N_NODES);
}

// round 14
// speedup vs baseline: 1.4070x; 1.4070x over previous
#include <cuda_runtime.h>
#include <cuda_fp16.h>
#include <cstdint>

#define N_NODES 100000
#define N_EDGES 1600000
#define CAP 64            // per-node neighbor bucket capacity (mean deg 16)

// -------- device scratch (static: no allocations allowed) --------
__device__ int   g_cursor[N_NODES];
__device__ int   g_col[N_NODES * CAP];
__device__ __align__(16) __half2 g_x16[N_NODES * 32];   // x in fp16 (64 ch)
__device__ __align__(16) __half2 g_h16[N_NODES * 64];   // h1 in fp16 (128 ch)
__device__ __align__(16) __half  g_z1h[N_NODES * 64];   // z1 fp16
__device__ __align__(16) __half  g_z2h[N_NODES * 128];  // z2 fp16
// Fragment-order packed fp16 weights (b32 units). Per matrix:
// index = ((kb*NTP + tp)*32 + lane)*4 + q; q selects {b0,b1 of t=2tp, b0,b1 of t=2tp+1}.
// Offsets (u32): W1a:0(4096) W1b:4096(8192) W2a:12288 W2b:20480 Wlin:28672(4096)
__device__ __align__(16) uint32_t g_wpk[32768];

// m16n8k16 fp16 MMA, fp32 accumulate (sm_70+ PTX, plain sm_103 OK)
__device__ __forceinline__ void mma_f16(float c[4],
                                        uint32_t a0, uint32_t a1,
                                        uint32_t a2, uint32_t a3,
                                        uint32_t b0, uint32_t b1) {
    asm volatile(
        "mma.sync.aligned.m16n8k16.row.col.f32.f16.f16.f32 "
        "{%0,%1,%2,%3}, {%4,%5,%6,%7}, {%8,%9}, {%0,%1,%2,%3};"
        : "+f"(c[0]), "+f"(c[1]), "+f"(c[2]), "+f"(c[3])
        : "r"(a0), "r"(a1), "r"(a2), "r"(a3), "r"(b0), "r"(b1));
}

// MMA over K: A halfs [row][ASTR] in smem (scalar frag loads),
// B packed fragment-order uint4 in smem (one LDS.128 per kb,tp).
template <int K, int ASTR, int NT>
__device__ __forceinline__ void do_mma16(const __half* __restrict__ As,
                                         const uint4* __restrict__ Bpk,
                                         float (&acc)[NT][4], int row0) {
    int lane = threadIdx.x & 31;
    int g = lane >> 2, tg = lane & 3;
    const uint32_t* Ar0 = (const uint32_t*)(As + (row0 + g) * ASTR);
    const uint32_t* Ar1 = (const uint32_t*)(As + (row0 + g + 8) * ASTR);
#pragma unroll
    for (int kb = 0; kb < K / 16; kb++) {
        int k0 = kb * 8;                      // b32 units
        uint32_t a0 = Ar0[k0 + tg];
        uint32_t a1 = Ar1[k0 + tg];
        uint32_t a2 = Ar0[k0 + tg + 4];
        uint32_t a3 = Ar1[k0 + tg + 4];
#pragma unroll
        for (int tp = 0; tp < NT / 2; tp++) {
            uint4 b = Bpk[(kb * (NT / 2) + tp) * 32 + lane];
            mma_f16(acc[2 * tp],     a0, a1, a2, a3, b.x, b.y);
            mma_f16(acc[2 * tp + 1], a0, a1, a2, a3, b.z, b.w);
        }
    }
}

// MMA with A fragments resident in registers; B packed fragment-order.
template <int NKB, int NT>
__device__ __forceinline__ void do_mma16_regA(const uint32_t (&af)[NKB][4],
                                              const uint4* __restrict__ Bpk,
                                              float (&acc)[NT][4]) {
    int lane = threadIdx.x & 31;
#pragma unroll
    for (int kb = 0; kb < NKB; kb++) {
#pragma unroll
        for (int tp = 0; tp < NT / 2; tp++) {
            uint4 b = Bpk[(kb * (NT / 2) + tp) * 32 + lane];
            mma_f16(acc[2 * tp],     af[kb][0], af[kb][1], af[kb][2], af[kb][3], b.x, b.y);
            mma_f16(acc[2 * tp + 1], af[kb][0], af[kb][1], af[kb][2], af[kb][3], b.z, b.w);
        }
    }
}

// relu(acc + bias) -> fp16 A-fragments for the next stage (pure register permute).
template <int NKB>
__device__ __forceinline__ void acc_to_afrag(const float (&acc)[2 * NKB][4],
                                             uint32_t (&af)[NKB][4],
                                             const float* __restrict__ bias) {
    int tg = threadIdx.x & 3;
#pragma unroll
    for (int kb = 0; kb < NKB; kb++) {
        int t0 = 2 * kb, t1 = 2 * kb + 1;
        float b00 = bias[t0 * 8 + 2 * tg], b01 = bias[t0 * 8 + 2 * tg + 1];
        float b10 = bias[t1 * 8 + 2 * tg], b11 = bias[t1 * 8 + 2 * tg + 1];
        __half2 h;
        h = __floats2half2_rn(fmaxf(acc[t0][0] + b00, 0.f), fmaxf(acc[t0][1] + b01, 0.f));
        af[kb][0] = *(uint32_t*)&h;
        h = __floats2half2_rn(fmaxf(acc[t0][2] + b00, 0.f), fmaxf(acc[t0][3] + b01, 0.f));
        af[kb][1] = *(uint32_t*)&h;
        h = __floats2half2_rn(fmaxf(acc[t1][0] + b10, 0.f), fmaxf(acc[t1][1] + b11, 0.f));
        af[kb][2] = *(uint32_t*)&h;
        h = __floats2half2_rn(fmaxf(acc[t1][2] + b10, 0.f), fmaxf(acc[t1][3] + b11, 0.f));
        af[kb][3] = *(uint32_t*)&h;
    }
}

// Epilogue -> global fp32 (final out): acc + bias, float2 stores, row-guarded
template <int NT, int NOUT>
__device__ __forceinline__ void st_glob(float* __restrict__ out,
                                        float (&acc)[NT][4], int grow0,
                                        const float* __restrict__ bias, int n) {
    int lane = threadIdx.x & 31;
    int g = lane >> 2, tg = lane & 3;
    int r0 = grow0 + g, r1 = r0 + 8;
#pragma unroll
    for (int t = 0; t < NT; t++) {
        int ch = t * 8 + 2 * tg;
        float bx = bias[ch], by = bias[ch + 1];
        if (r0 < n) *(float2*)&out[r0 * NOUT + ch] = make_float2(acc[t][0] + bx, acc[t][1] + by);
        if (r1 < n) *(float2*)&out[r1 * NOUT + ch] = make_float2(acc[t][2] + bx, acc[t][3] + by);
    }
}

// Epilogue -> global fp16 (h1): relu(acc + bias) as half2, row-guarded
template <int NT>
__device__ __forceinline__ void st_glob_h16(__half2* __restrict__ out,
                                            float (&acc)[NT][4], int grow0,
                                            const float* __restrict__ bias, int n) {
    int lane = threadIdx.x & 31;
    int g = lane >> 2, tg = lane & 3;
    int r0 = grow0 + g, r1 = r0 + 8;
#pragma unroll
    for (int t = 0; t < NT; t++) {
        int ch = t * 8 + 2 * tg;      // even
        float bx = bias[ch], by = bias[ch + 1];
        if (r0 < n) out[r0 * 64 + (ch >> 1)] =
            __floats2half2_rn(fmaxf(acc[t][0] + bx, 0.f), fmaxf(acc[t][1] + by, 0.f));
        if (r1 < n) out[r1 * 64 + (ch >> 1)] =
            __floats2half2_rn(fmaxf(acc[t][2] + bx, 0.f), fmaxf(acc[t][3] + by, 0.f));
    }
}

// ==================== init: zero cursors + fragment-order packed weights ==========
__global__ void k_init(const float* __restrict__ W1a, const float* __restrict__ W1b,
                       const float* __restrict__ W2a, const float* __restrict__ W2b,
                       const float* __restrict__ Wlin) {
    int i = blockIdx.x * 256 + threadIdx.x;
    if (i < N_NODES) g_cursor[i] = 0;
    if (i < 32768) {
        const float* W; int NOUT, NTP, base;
        if (i < 4096)       { W = W1a;  NOUT = 128; NTP = 8; base = 0; }
        else if (i < 12288) { W = W1b;  NOUT = 128; NTP = 8; base = 4096; }
        else if (i < 20480) { W = W2a;  NOUT = 128; NTP = 8; base = 12288; }
        else if (i < 28672) { W = W2b;  NOUT = 128; NTP = 8; base = 20480; }
        else                { W = Wlin; NOUT = 64;  NTP = 4; base = 28672; }
        int rem = i - base;
        int q = rem & 3, lane = (rem >> 2) & 31, rest = rem >> 7;
        int tp = rest % NTP, kb = rest / NTP;
        int g = lane >> 2, tg = lane & 3;
        int t = 2 * tp + (q >> 1);
        int k = kb * 16 + (q & 1) * 8 + 2 * tg;
        int ch = t * 8 + g;
        __half2 hv = __floats2half2_rn(W[k * NOUT + ch], W[(k + 1) * NOUT + ch]);
        g_wpk[i] = *(uint32_t*)&hv;
    }
}

// ==================== bucket fill (no scan) + x -> fp16 convert ====================
__global__ void k_fill(const int* __restrict__ ei, const float* __restrict__ x) {
    int e = blockIdx.x * 256 + threadIdx.x;     // 1.6M threads
    if (e < N_EDGES) {
        int d = ei[N_EDGES + e];
        int s = ei[e];
        int p = atomicAdd(&g_cursor[d], 1);
        if (p < CAP) g_col[d * CAP + p] = s;
    }
    const float4* x4 = (const float4*)x;
    float4 v = x4[e];                            // e < 1.6M exactly covers x
    g_x16[e * 2]     = __floats2half2_rn(v.x, v.y);
    g_x16[e * 2 + 1] = __floats2half2_rn(v.z, v.w);
}

// ==================== Aggregation (fp16 gather, fp32 accumulate) ====================

// d=64: warp per node; 16 lanes x uint2 = one 128B line/edge; half-warp interleave.
__global__ void __launch_bounds__(256) k_agg64(const float* __restrict__ x) {
    int node = (blockIdx.x * 256 + threadIdx.x) >> 5;
    int lane = threadIdx.x & 31;
    int c = lane & 15;
    int h = lane >> 4;
    int deg = min(g_cursor[node], CAP);
    int base = node * CAP;
    float4 acc = make_float4(0.f, 0.f, 0.f, 0.f);
    const uint2* x16 = (const uint2*)g_x16;
    for (int p = h; p < deg; p += 2) {
        int s = __ldg(&g_col[base + p]);
        uint2 u = x16[s * 16 + c];
        float2 f0 = __half22float2(*(__half2*)&u.x);
        float2 f1 = __half22float2(*(__half2*)&u.y);
        acc.x += f0.x; acc.y += f0.y; acc.z += f1.x; acc.w += f1.y;
    }
    acc.x += __shfl_xor_sync(0xffffffffu, acc.x, 16);
    acc.y += __shfl_xor_sync(0xffffffffu, acc.y, 16);
    acc.z += __shfl_xor_sync(0xffffffffu, acc.z, 16);
    acc.w += __shfl_xor_sync(0xffffffffu, acc.w, 16);
    if (h == 0) {
        float4 xi = ((const float4*)x)[node * 16 + c];
        uint2 o;
        *(__half2*)&o.x = __floats2half2_rn(xi.x + acc.x, xi.y + acc.y);
        *(__half2*)&o.y = __floats2half2_rn(xi.z + acc.z, xi.w + acc.w);
        ((uint2*)g_z1h)[node * 16 + c] = o;
    }
}

// d=128: warp per node; 32 lanes x uint2 = 256B/edge; unroll 2.
__global__ void __launch_bounds__(256) k_agg128() {
    int node = (blockIdx.x * 256 + threadIdx.x) >> 5;
    int lane = threadIdx.x & 31;
    int deg = min(g_cursor[node], CAP);
    int base = node * CAP;
    const uint2* h16 = (const uint2*)g_h16;
    float4 a0 = make_float4(0.f, 0.f, 0.f, 0.f);
    float4 a1 = make_float4(0.f, 0.f, 0.f, 0.f);
    int p = 0;
    for (; p + 1 < deg; p += 2) {
        int s0 = __ldg(&g_col[base + p]);
        int s1 = __ldg(&g_col[base + p + 1]);
        uint2 u0 = h16[s0 * 32 + lane];
        uint2 u1 = h16[s1 * 32 + lane];
        float2 f00 = __half22float2(*(__half2*)&u0.x);
        float2 f01 = __half22float2(*(__half2*)&u0.y);
        float2 f10 = __half22float2(*(__half2*)&u1.x);
        float2 f11 = __half22float2(*(__half2*)&u1.y);
        a0.x += f00.x; a0.y += f00.y; a0.z += f01.x; a0.w += f01.y;
        a1.x += f10.x; a1.y += f10.y; a1.z += f11.x; a1.w += f11.y;
    }
    if (p < deg) {
        int s0 = __ldg(&g_col[base + p]);
        uint2 u0 = h16[s0 * 32 + lane];
        float2 f00 = __half22float2(*(__half2*)&u0.x);
        float2 f01 = __half22float2(*(__half2*)&u0.y);
        a0.x += f00.x; a0.y += f00.y; a0.z += f01.x; a0.w += f01.y;
    }
    uint2 us = h16[node * 32 + lane];
    float2 s0 = __half22float2(*(__half2*)&us.x);
    float2 s1 = __half22float2(*(__half2*)&us.y);
    uint2 o;
    *(__half2*)&o.x = __floats2half2_rn(s0.x + a0.x + a1.x, s0.y + a0.y + a1.y);
    *(__half2*)&o.y = __floats2half2_rn(s1.x + a0.z + a1.z, s1.y + a0.w + a1.w);
    ((uint2*)g_z2h)[node * 32 + lane] = o;
}

// ==================== Fused MLP kernels (packed-B + register-resident mid) =========
// 256 threads = 8 warps; warp w owns rows w*16..w*16+15, ALL 128 output channels.

// conv1: h1(fp16) = relu( relu(z1@W1a+b1a) @ W1b + b1b )
__global__ void __launch_bounds__(256, 2)
k_mlp1(const float* __restrict__ b1a, const float* __restrict__ b1b, int n) {
    extern __shared__ __align__(16) char smraw[];
    __half*   A    = (__half*)smraw;                 // 128 x 72 halfs (z1 tile)
    uint32_t* WaPK = (uint32_t*)(smraw + 128 * 72 * 2);   // 4096 u32
    uint32_t* WbPK = WaPK + 4096;                         // 8192 u32

    int tid = threadIdx.x;
    int m0 = blockIdx.x * 128;

    for (int i = tid; i < 128 * 16; i += 256) {
        int row = i >> 4, j = i & 15;
        int node = m0 + row;
        uint2 v = make_uint2(0u, 0u);
        if (node < n) v = ((const uint2*)g_z1h)[node * 16 + j];
        *(uint2*)&A[row * 72 + j * 4] = v;
    }
    for (int i = tid; i < 1024; i += 256)
        ((uint4*)WaPK)[i] = ((const uint4*)g_wpk)[i];
    for (int i = tid; i < 2048; i += 256)
        ((uint4*)WbPK)[i] = ((const uint4*)(g_wpk + 4096))[i];
    __syncthreads();

    int row0 = (tid >> 5) * 16;

    float acc1[16][4];
#pragma unroll
    for (int t = 0; t < 16; t++)
        acc1[t][0] = acc1[t][1] = acc1[t][2] = acc1[t][3] = 0.f;
    do_mma16<64, 72, 16>(A, (const uint4*)WaPK, acc1, row0);

    uint32_t af[8][4];
    acc_to_afrag<8>(acc1, af, b1a);

    float acc2[16][4];
#pragma unroll
    for (int t = 0; t < 16; t++)
        acc2[t][0] = acc2[t][1] = acc2[t][2] = acc2[t][3] = 0.f;
    do_mma16_regA<8, 16>(af, (const uint4*)WbPK, acc2);
    st_glob_h16<16>(g_h16, acc2, m0 + row0, b1b, n);
}

// conv2 + final: out = relu( relu(z2@W2a+b2a) @ W2b + b2b ) @ Wlin + blin
__global__ void __launch_bounds__(256, 2)
k_mlp2(const float* __restrict__ b2a, const float* __restrict__ b2b,
       const float* __restrict__ blin, float* __restrict__ out, int n) {
    extern __shared__ __align__(16) char smraw[];
    __half*   RA = (__half*)smraw;                   // 128 x 136 halfs (z2 tile)
    uint32_t* RB = (uint32_t*)(smraw + 128 * 136 * 2);    // 8192 u32: W2aPK -> WlinPK
    uint32_t* RC = RB + 8192;                             // 8192 u32: W2bPK

    int tid = threadIdx.x;
    int m0 = blockIdx.x * 128;

    for (int i = tid; i < 128 * 16; i += 256) {
        int row = i >> 4, j = i & 15;
        int node = m0 + row;
        uint4 v = make_uint4(0u, 0u, 0u, 0u);
        if (node < n) v = ((const uint4*)g_z2h)[node * 16 + j];
        *(uint4*)&RA[row * 136 + j * 8] = v;
    }
    for (int i = tid; i < 2048; i += 256) {
        ((uint4*)RB)[i] = ((const uint4*)(g_wpk + 12288))[i];
        ((uint4*)RC)[i] = ((const uint4*)(g_wpk + 20480))[i];
    }
    __syncthreads();

    int row0 = (tid >> 5) * 16;

    // stage 1: mid = relu(z2 @ W2a + b2a)   (mid -> registers)
    float acc1[16][4];
#pragma unroll
    for (int t = 0; t < 16; t++)
        acc1[t][0] = acc1[t][1] = acc1[t][2] = acc1[t][3] = 0.f;
    do_mma16<128, 136, 16>(RA, (const uint4*)RB, acc1, row0);
    uint32_t af1[8][4];
    acc_to_afrag<8>(acc1, af1, b2a);
    __syncthreads();                 // all reads of RB (W2aPK) done

    // overlap: load WlinPK into RB while stage-2 MMAs run
    for (int i = tid; i < 1024; i += 256)
        ((uint4*)RB)[i] = ((const uint4*)(g_wpk + 28672))[i];

    // stage 2: h = relu(mid @ W2b + b2b)    (h -> registers)
    float acc2[16][4];
#pragma unroll
    for (int t = 0; t < 16; t++)
        acc2[t][0] = acc2[t][1] = acc2[t][2] = acc2[t][3] = 0.f;
    do_mma16_regA<8, 16>(af1, (const uint4*)RC, acc2);
    uint32_t af2[8][4];
    acc_to_afrag<8>(acc2, af2, b2b);
    __syncthreads();                 // WlinPK visible

    // stage 3: out = h @ Wlin + blin   (NOUT=64, NT=8)
    float acc3[8][4];
#pragma unroll
    for (int t = 0; t < 8; t++)
        acc3[t][0] = acc3[t][1] = acc3[t][2] = acc3[t][3] = 0.f;
    do_mma16_regA<8, 8>(af2, (const uint4*)RB, acc3);
    st_glob<8, 64>(out, acc3, m0 + row0, blin, n);
}

// ==================== host orchestration ====================

extern "C" void kernel_launch(void* const* d_in, const int* in_sizes, int n_in,
                              void* d_out, int out_size) {
    const float* x    = (const float*)d_in[0];
    const int*   ei   = (const int*)d_in[1];
    const float* W1a  = (const float*)d_in[2];
    const float* b1a  = (const float*)d_in[3];
    const float* W1b  = (const float*)d_in[4];
    const float* b1b  = (const float*)d_in[5];
    const float* W2a  = (const float*)d_in[6];
    const float* b2a  = (const float*)d_in[7];
    const float* W2b  = (const float*)d_in[8];
    const float* b2b  = (const float*)d_in[9];
    const float* Wlin = (const float*)d_in[10];
    const float* blin = (const float*)d_in[11];
    float*       out  = (float*)d_out;

    const int SM1 = 128 * 72 * 2 + 4096 * 4 + 8192 * 4;   // 67584
    const int SM2 = 128 * 136 * 2 + 2 * 8192 * 4;         // 100352
    cudaFuncSetAttribute(k_mlp1, cudaFuncAttributeMaxDynamicSharedMemorySize, SM1);
    cudaFuncSetAttribute(k_mlp2, cudaFuncAttributeMaxDynamicSharedMemorySize, SM2);

    const int GN   = (N_NODES + 255) / 256;   // 391
    const int GE   = (N_EDGES + 255) / 256;   // 6250
    const int GW   = N_NODES / 8;             // 12500
    const int GB128 = (N_NODES + 127) / 128;  // 782

    // --- init + bucket fill (+ x->fp16) ---
    k_init<<<GN, 256>>>(W1a, W1b, W2a, W2b, Wlin);
    k_fill<<<GE, 256>>>(ei, x);

    // --- conv1 ---
    k_agg64<<<GW, 256>>>(x);
    k_mlp1<<<GB128, 256, SM1>>>(b1a, b1b, N_NODES);

    // --- conv2 + final projection ---
    k_agg128<<<GW, 256>>>();
    k_mlp2<<<GB128, 256, SM2>>>(b2a, b2b, blin, out, N_NODES);
}